// round 3
// baseline (speedup 1.0000x reference)
#include <cuda_runtime.h>
#include <cstdint>
#include <cstddef>
#include <math.h>

#define SEQ    2048
#define BATCH  64
#define HID    512
#define NCTA   128
#define NTHR   256

typedef unsigned long long u64;

// ---------------- device globals (allocation-free scratch) ----------------
__device__ unsigned g_arrive = 0;
__device__ unsigned g_phase  = 0;
__device__ float g_h0_all[(size_t)SEQ * BATCH * HID];  // 256 MB layer-0 hidden states
__device__ float g_h1_all[(size_t)SEQ * BATCH * HID];  // 256 MB layer-1 hidden states

// ---------------- packed fp32x2 helpers (Blackwell FFMA2 path) ----------------
__device__ __forceinline__ u64 ffma2(u64 a, u64 b, u64 c) {
    u64 d;
    asm("fma.rn.f32x2 %0, %1, %2, %3;" : "=l"(d) : "l"(a), "l"(b), "l"(c));
    return d;
}
__device__ __forceinline__ u64 fadd2(u64 a, u64 b) {
    u64 d;
    asm("add.rn.f32x2 %0, %1, %2;" : "=l"(d) : "l"(a), "l"(b));
    return d;
}
__device__ __forceinline__ u64 splat2(float x) {
    u64 d;
    asm("mov.b64 %0, {%1, %1};" : "=l"(d) : "f"(x));
    return d;
}
__device__ __forceinline__ float f2lo(u64 v) { return __uint_as_float((unsigned)v); }
__device__ __forceinline__ float f2hi(u64 v) { return __uint_as_float((unsigned)(v >> 32)); }

__device__ __forceinline__ u64 shflx64(u64 v, int m) {
    unsigned lo = (unsigned)v, hi = (unsigned)(v >> 32);
    lo = __shfl_xor_sync(0xffffffffu, lo, m);
    hi = __shfl_xor_sync(0xffffffffu, hi, m);
    return ((u64)hi << 32) | (u64)lo;
}
__device__ __forceinline__ unsigned ld_acq(unsigned* p) {
    unsigned v;
    asm volatile("ld.acquire.gpu.u32 %0, [%1];" : "=r"(v) : "l"(p));
    return v;
}
__device__ __forceinline__ float sigf(float x) { return 1.0f / (1.0f + expf(-x)); }

// =====================================================================
// Persistent fused LSTM layer.
//  Grid = 128 CTAs = 64 row-tiles x 2 batch-halves, 256 threads each.
//  CTA: 8 hidden units (32 gate rows, PyTorch i,f,g,o order) x 32 batches.
//  Combined weights [w_hh | w_ih] (K = 512+DIN) SMEM-resident, swizzled.
//  Threads: 16 k-groups x 4 row-groups x 4 batch-groups; 8x8 micro-tile,
//  accumulators packed as f32x2 hidden-unit pairs -> FFMA2.
//  One software grid barrier per timestep (epoch-relative, replay-safe).
// =====================================================================
template<int DIN>
__global__ void __launch_bounds__(NTHR, 1)
lstm_layer(const float* __restrict__ x,       // [SEQ][BATCH][DIN]
           const float* __restrict__ h0l,     // [BATCH][HID]
           const float* __restrict__ c0l,     // [BATCH][HID]
           const float* __restrict__ w_ih,    // [4H][DIN]
           const float* __restrict__ w_hh,    // [4H][HID]
           const float* __restrict__ b_ih,    // [4H]
           const float* __restrict__ b_hh,    // [4H]
           float* __restrict__ h_all)         // [SEQ][BATCH][HID]
{
    constexpr int K  = HID + DIN;
    constexpr int NC = K / 128;                 // 128-k chunks per step

    extern __shared__ float smem[];
    float* w_sm    = smem;                      // K * 32
    float* act_sm  = w_sm + K * 32;             // 128 * 33
    float* bias_sm = act_sm + 128 * 33;         // 32

    const int tid = threadIdx.x;
    const int kg  = tid & 15;                   // k-group 0..15
    const int sub = (tid >> 4) & 1;
    const int wrp = tid >> 5;
    const int rg  = wrp & 3;                    // row-group 0..3 (2 hu each)
    const int bg  = sub + ((wrp >> 2) << 1);    // batch-group 0..3 (8 b each)
    const int hu_base = (blockIdx.x >> 1) * 8;
    const int bbase   = (blockIdx.x & 1) * 32;

    // ---- one-time: weights (swizzled) + bias into SMEM ----
    for (int idx = tid; idx < 32 * K; idx += NTHR) {
        int k  = idx >> 5;
        int rp = idx & 31;                      // local row: gate*8 + hu_local
        int gate = rp >> 3, hl = rp & 7;
        int R = gate * HID + hu_base + hl;
        float v = (k < HID) ? w_hh[(size_t)R * HID + k]
                            : w_ih[(size_t)R * DIN + (k - HID)];
        int col = ((((rp >> 1) ^ (k & 15)) << 1) | (rp & 1));
        w_sm[k * 32 + col] = v;
    }
    if (tid < 32) {
        int gate = tid >> 3, hl = tid & 7;
        int R = gate * HID + hu_base + hl;
        bias_sm[tid] = b_ih[R] + b_hh[R];
    }

    // per-thread owned output cell after reduction
    const int hu_l = kg & 1;
    const int b_l  = kg >> 1;
    const int hl_o = rg * 2 + hu_l;             // hidden unit local 0..7
    const int bb_o = bg * 8 + b_l;              // batch local 0..31
    float c_reg = c0l[(size_t)(bbase + bb_o) * HID + hu_base + hl_o];

    // swizzled weight columns for this thread's 4 gate row-pairs
    int colg[4];
#pragma unroll
    for (int g = 0; g < 4; g++) colg[g] = ((g * 4 + rg) ^ kg) << 1;

    __shared__ unsigned s_p0;
    if (tid == 0) s_p0 = ld_acq(&g_phase);
    __syncthreads();                            // covers weights/bias too
    const unsigned phase0 = s_p0;

    float stg[16];

    for (int t = 0; t < SEQ; ++t) {
        const float* __restrict__ hprev =
            (t == 0) ? h0l : (h_all + (size_t)(t - 1) * BATCH * HID);
        const float* __restrict__ xt = x + (size_t)t * BATCH * DIN;

        u64 acc[4][8];
#pragma unroll
        for (int g = 0; g < 4; g++)
#pragma unroll
            for (int b = 0; b < 8; b++) acc[g][b] = 0ull;

        // prefetch chunk 0 (always h-region: K >= 512)
#pragma unroll
        for (int p = 0; p < 4; p++) {
            int idx = p * NTHR + tid;
            int b = idx >> 5, s = idx & 31;
            const float* gsrc = hprev + (size_t)(bbase + b) * HID + s;
#pragma unroll
            for (int q = 0; q < 4; q++) stg[p * 4 + q] = __ldg(gsrc + 32 * q);
        }

        for (int c = 0; c < NC; ++c) {
            // stage chunk c: strided STS, conflict-free with stride-33 layout
#pragma unroll
            for (int p = 0; p < 4; p++) {
                int idx = p * NTHR + tid;
                int b = idx >> 5, s = idx & 31;
#pragma unroll
                for (int q = 0; q < 4; q++)
                    act_sm[(s + 32 * q) * 33 + b] = stg[p * 4 + q];
            }
            __syncthreads();

            // prefetch chunk c+1 into registers
            if (c + 1 < NC) {
                int cn = c + 1;
                const float* src; int stride, koff;
                if (cn < 4) { src = hprev; stride = HID; koff = cn * 128; }
                else        { src = xt;    stride = DIN; koff = cn * 128 - HID; }
#pragma unroll
                for (int p = 0; p < 4; p++) {
                    int idx = p * NTHR + tid;
                    int b = idx >> 5, s = idx & 31;
                    const float* gsrc = src + (size_t)(bbase + b) * stride + koff + s;
#pragma unroll
                    for (int q = 0; q < 4; q++) stg[p * 4 + q] = __ldg(gsrc + 32 * q);
                }
            }

            // compute chunk c: 8 strided k per k-group
            const int wbase = (c * 128 + kg) * 32;
            const int abase = kg * 33 + bg * 8;
#pragma unroll
            for (int j = 0; j < 8; ++j) {
                u64 w2[4];
#pragma unroll
                for (int g = 0; g < 4; g++)
                    w2[g] = *reinterpret_cast<const u64*>(
                        w_sm + wbase + j * (16 * 32) + colg[g]);
                float a[8];
#pragma unroll
                for (int b = 0; b < 8; b++)
                    a[b] = act_sm[abase + j * (16 * 33) + b];
#pragma unroll
                for (int b = 0; b < 8; b++) {
                    u64 a2 = splat2(a[b]);
#pragma unroll
                    for (int g = 0; g < 4; g++)
                        acc[g][b] = ffma2(w2[g], a2, acc[g][b]);
                }
            }
            __syncthreads();
        }

        // butterfly reduction over the 16 k-group lanes
#pragma unroll
        for (int m = 1; m < 16; m <<= 1) {
#pragma unroll
            for (int g = 0; g < 4; g++)
#pragma unroll
                for (int b = 0; b < 8; b++)
                    acc[g][b] = fadd2(acc[g][b], shflx64(acc[g][b], m));
        }

        // gate nonlinearities + cell update (each lane owns one (hu, b) cell)
        float gv[4];
#pragma unroll
        for (int g = 0; g < 4; g++) {
            u64 v = acc[g][b_l];
            gv[g] = (hu_l ? f2hi(v) : f2lo(v)) + bias_sm[g * 8 + hl_o];
        }
        float ig = sigf(gv[0]);
        float fg = sigf(gv[1]);
        float gg = tanhf(gv[2]);
        float og = sigf(gv[3]);
        c_reg = fg * c_reg + ig * gg;
        float hv = og * tanhf(c_reg);
        h_all[((size_t)t * BATCH + (bbase + bb_o)) * HID + hu_base + hl_o] = hv;

        // grid barrier (skip after last step)
        if (t + 1 < SEQ) {
            __threadfence();
            __syncthreads();
            if (tid == 0) {
                unsigned target = phase0 + (unsigned)(t + 1);
                unsigned old = atomicAdd(&g_arrive, 1u);
                if (old == (unsigned)(NCTA - 1)) {
                    g_arrive = 0u;
                    __threadfence();
                    atomicAdd(&g_phase, 1u);
                } else {
                    while ((int)(ld_acq(&g_phase) - target) < 0) __nanosleep(64);
                }
            }
            __syncthreads();
        }
    }
}

// ---------------- output head: sigmoid(h1 . w_out + b_out) ----------------
__global__ void __launch_bounds__(256)
head_kernel(const float* __restrict__ h_all, const float* __restrict__ w_out,
            const float* __restrict__ b_out, float* __restrict__ out)
{
    __shared__ float wsm[HID];
    int t = blockIdx.x;
    for (int i = threadIdx.x; i < HID; i += 256) wsm[i] = w_out[i];
    __syncthreads();
    int wrp = threadIdx.x >> 5, lane = threadIdx.x & 31;
    float bo = b_out[0];
#pragma unroll
    for (int rb = 0; rb < 8; ++rb) {
        int b = wrp * 8 + rb;
        const float* h = h_all + ((size_t)t * BATCH + b) * HID;
        float s = 0.f;
#pragma unroll
        for (int j = 0; j < 16; ++j) s += h[lane + 32 * j] * wsm[lane + 32 * j];
#pragma unroll
        for (int m = 16; m > 0; m >>= 1) s += __shfl_xor_sync(0xffffffffu, s, m);
        if (lane == 0) out[(size_t)t * BATCH + b] = 1.f / (1.f + expf(-(s + bo)));
    }
}

extern "C" void kernel_launch(void* const* d_in, const int* in_sizes, int n_in,
                              void* d_out, int out_size)
{
    (void)in_sizes; (void)n_in; (void)out_size;
    const float* input = (const float*)d_in[0];
    const float* h0    = (const float*)d_in[1];
    const float* c0    = (const float*)d_in[2];
    const float* w_ih0 = (const float*)d_in[3];
    const float* w_hh0 = (const float*)d_in[4];
    const float* b_ih0 = (const float*)d_in[5];
    const float* b_hh0 = (const float*)d_in[6];
    const float* w_ih1 = (const float*)d_in[7];
    const float* w_hh1 = (const float*)d_in[8];
    const float* b_ih1 = (const float*)d_in[9];
    const float* b_hh1 = (const float*)d_in[10];
    const float* w_out = (const float*)d_in[11];
    const float* b_out = (const float*)d_in[12];
    float* out = (float*)d_out;

    float* h0p = nullptr;
    float* h1p = nullptr;
    cudaGetSymbolAddress((void**)&h0p, g_h0_all);
    cudaGetSymbolAddress((void**)&h1p, g_h1_all);

    const int smem0 = (768  * 32 + 128 * 33 + 32) * (int)sizeof(float);  // 115,328 B
    const int smem1 = (1024 * 32 + 128 * 33 + 32) * (int)sizeof(float);  // 148,096 B
    cudaFuncSetAttribute(lstm_layer<256>, cudaFuncAttributeMaxDynamicSharedMemorySize, smem0);
    cudaFuncSetAttribute(lstm_layer<512>, cudaFuncAttributeMaxDynamicSharedMemorySize, smem1);

    lstm_layer<256><<<NCTA, NTHR, smem0>>>(input, h0, c0,
                                           w_ih0, w_hh0, b_ih0, b_hh0, h0p);
    lstm_layer<512><<<NCTA, NTHR, smem1>>>(h0p, h0 + BATCH * HID, c0 + BATCH * HID,
                                           w_ih1, w_hh1, b_ih1, b_hh1, h1p);
    head_kernel<<<SEQ, 256>>>(h1p, w_out, b_out, out);
}

// round 4
// speedup vs baseline: 2.0219x; 2.0219x over previous
#include <cuda_runtime.h>
#include <cstdint>
#include <cstddef>
#include <math.h>

#define SEQ    2048
#define BATCH  64
#define HID    512
#define NCTA   128
#define NTHR   512

typedef unsigned long long u64;

// ---------------- device globals (allocation-free scratch) ----------------
__device__ unsigned g_arrive = 0;
__device__ unsigned g_phase  = 0;
__device__ float g_h0_all[(size_t)SEQ * BATCH * HID];
__device__ float g_h1_all[(size_t)SEQ * BATCH * HID];

// ---------------- packed fp32x2 helpers ----------------
__device__ __forceinline__ u64 ffma2(u64 a, u64 b, u64 c) {
    u64 d;
    asm("fma.rn.f32x2 %0, %1, %2, %3;" : "=l"(d) : "l"(a), "l"(b), "l"(c));
    return d;
}
__device__ __forceinline__ u64 fadd2(u64 a, u64 b) {
    u64 d;
    asm("add.rn.f32x2 %0, %1, %2;" : "=l"(d) : "l"(a), "l"(b));
    return d;
}
__device__ __forceinline__ u64 splat2(float x) {
    u64 d;
    asm("mov.b64 %0, {%1, %1};" : "=l"(d) : "f"(x));
    return d;
}
__device__ __forceinline__ float f2lo(u64 v) { return __uint_as_float((unsigned)v); }
__device__ __forceinline__ float f2hi(u64 v) { return __uint_as_float((unsigned)(v >> 32)); }

__device__ __forceinline__ u64 shflx64(u64 v, int m) {
    unsigned lo = (unsigned)v, hi = (unsigned)(v >> 32);
    lo = __shfl_xor_sync(0xffffffffu, lo, m);
    hi = __shfl_xor_sync(0xffffffffu, hi, m);
    return ((u64)hi << 32) | (u64)lo;
}
__device__ __forceinline__ u64 shfli64(u64 v, int src) {
    unsigned lo = (unsigned)v, hi = (unsigned)(v >> 32);
    lo = __shfl_sync(0xffffffffu, lo, src);
    hi = __shfl_sync(0xffffffffu, hi, src);
    return ((u64)hi << 32) | (u64)lo;
}
__device__ __forceinline__ unsigned ld_acq(unsigned* p) {
    unsigned v;
    asm volatile("ld.acquire.gpu.u32 %0, [%1];" : "=r"(v) : "l"(p));
    return v;
}
__device__ __forceinline__ float sigf(float x) { return 1.0f / (1.0f + __expf(-x)); }
__device__ __forceinline__ float tanhfast(float x) {
    // tanh(x) = 2*sigmoid(2x) - 1
    return 2.0f / (1.0f + __expf(-2.0f * x)) - 1.0f;
}

// =====================================================================
// Persistent fused LSTM layer, v2.
//  128 CTAs x 512 threads. CTA: 8 hu (32 gate rows) x 32 batches.
//  Warp (rg,bg) in 4x4; lane = k-split-32. Micro-tile: 4 gate-pairs x
//  8 batches of f32x2 (32 accs) -> FFMA2, crossbar/FMA co-limited.
//  Whole-K activation staged once per step (L0) / two 512 chunks (L1).
//  Selection-compaction warp reduction (62 SHFL), f32x2 cell update.
// =====================================================================
template<int DIN>
__global__ void __launch_bounds__(NTHR, 1)
lstm_layer(const float* __restrict__ x,       // [SEQ][BATCH][DIN]
           const float* __restrict__ h0l,     // [BATCH][HID]
           const float* __restrict__ c0l,     // [BATCH][HID]
           const float* __restrict__ w_ih,    // [4H][DIN]
           const float* __restrict__ w_hh,    // [4H][HID]
           const float* __restrict__ b_ih,    // [4H]
           const float* __restrict__ b_hh,    // [4H]
           float* __restrict__ h_all)         // [SEQ][BATCH][HID]
{
    constexpr int K    = HID + DIN;                 // 768 or 1024
    constexpr int ACTK = (K == 768) ? 768 : 512;    // act chunk size
    constexpr int NCH  = K / ACTK;                  // 1 or 2
    constexpr int JN   = ACTK / 32;                 // 24 or 16

    extern __shared__ float smem[];
    float* w_sm    = smem;                          // K*32
    float* act_sm  = w_sm + K * 32;                 // ACTK*33
    float* bias_sm = act_sm + ACTK * 33;            // 32 (pair-major)

    const int tid  = threadIdx.x;
    const int lane = tid & 31;
    const int wrp  = tid >> 5;                      // 0..15
    const int rg   = wrp & 3;                       // hu-pair group
    const int bg   = wrp >> 2;                      // batch group (8 each)
    const int hu_base = (blockIdx.x >> 1) * 8;
    const int bbase   = (blockIdx.x & 1) * 32;

    // ---- one-time: weights (swizzled, coalesced per-row) + bias ----
    for (int r = 0; r < 32; r++) {
        int gate = r >> 3, hl = r & 7;
        int R = gate * HID + hu_base + hl;
        int pair = gate * 4 + (hl >> 1);
        const float* wr_h = w_hh + (size_t)R * HID;
        const float* wr_x = w_ih + (size_t)R * DIN;
        for (int k = tid; k < K; k += NTHR) {
            float v = (k < HID) ? wr_h[k] : wr_x[k - HID];
            int col = ((pair ^ (k & 15)) << 1) | (hl & 1);
            w_sm[k * 32 + col] = v;
        }
    }
    if (tid < 32) {
        int gate = tid >> 3, hl = tid & 7;
        int R = gate * HID + hu_base + hl;
        int pair = gate * 4 + (hl >> 1);
        bias_sm[pair * 2 + (hl & 1)] = b_ih[R] + b_hh[R];
    }

    __shared__ unsigned s_p0;
    if (tid == 0) s_p0 = ld_acq(&g_phase);
    __syncthreads();                                // also covers weights/bias
    const unsigned phase0 = s_p0;

    u64 bias2[4];
#pragma unroll
    for (int g = 0; g < 4; g++)
        bias2[g] = ((const u64*)bias_sm)[g * 4 + rg];

    // per-thread addressing
    int colg[4];
#pragma unroll
    for (int g = 0; g < 4; g++) colg[g] = (((g * 4 + rg) ^ (lane & 15)) << 1);
    const float* abase = act_sm + lane * 33 + bg * 8;

    // owned output cell: hu pair (hu_base + 2*rg, +1), batch bg*8 + (lane&7)
    const int bb  = bg * 8 + (lane & 7);
    const int hu0 = hu_base + rg * 2;
    float c0r = c0l[(size_t)(bbase + bb) * HID + hu0];
    float c1r = c0l[(size_t)(bbase + bb) * HID + hu0 + 1];

    const int sb = lane;                            // staging k-lane
    const int b0 = (tid >> 5);                      // staging batch p=0
#define ACCF(i) acc[(i) >> 3][(i) & 7]

    for (int t = 0; t < SEQ; ++t) {
        const float* __restrict__ hprev =
            t ? (h_all + (size_t)(t - 1) * BATCH * HID) : h0l;
        const float* __restrict__ xt = x + (size_t)t * BATCH * DIN;

        u64 acc[4][8];
#pragma unroll
        for (int g = 0; g < 4; g++)
#pragma unroll
            for (int b = 0; b < 8; b++) acc[g][b] = 0ull;

#pragma unroll
        for (int ch = 0; ch < NCH; ++ch) {
            const int kbase = ch * ACTK;
            // qh: number of 32-k groups in this chunk coming from hprev
            const int qh = (HID > kbase) ? ((HID - kbase) / 32 < JN ?
                                            (HID - kbase) / 32 : JN) : 0;
            // ---- stage chunk ch ----
#pragma unroll
            for (int p = 0; p < 2; p++) {
                const int b = b0 + p * 16;
                const float* hrow = hprev + (size_t)(bbase + b) * HID;
                const float* xrow = xt + (size_t)(bbase + b) * DIN;
                float* arow = act_sm + sb * 33 + b;
#pragma unroll 8
                for (int q = 0; q < qh; q++)
                    arow[q * (32 * 33)] = __ldg(hrow + kbase + q * 32 + sb);
#pragma unroll 8
                for (int q = qh; q < JN; q++)
                    arow[q * (32 * 33)] = __ldg(xrow + kbase + q * 32 + sb - HID);
            }
            __syncthreads();

            // ---- compute chunk ch ----
            const float* wl = w_sm + kbase * 32 + lane * 32;
#pragma unroll
            for (int j = 0; j < JN; j++) {
                u64 w2[4];
#pragma unroll
                for (int g = 0; g < 4; g++)
                    w2[g] = *(const u64*)(wl + j * (32 * 32) + colg[g]);
                float a[8];
#pragma unroll
                for (int b = 0; b < 8; b++)
                    a[b] = abase[j * (32 * 33) + b];
#pragma unroll
                for (int b = 0; b < 8; b++) {
                    u64 a2 = splat2(a[b]);
#pragma unroll
                    for (int g = 0; g < 4; g++)
                        acc[g][b] = ffma2(w2[g], a2, acc[g][b]);
                }
            }
            if (ch + 1 < NCH) __syncthreads();      // act buffer reuse
        }

        // ---- selection-compaction reduction over 32 k-lanes ----
        // After: lane l holds total for flat idx l (g = l>>3, b = l&7).
#pragma unroll
        for (int i = 0; i < 16; i++) {
            u64 lo = ACCF(i), hi = ACCF(i + 16);
            u64 mine = (lane & 16) ? hi : lo;
            u64 give = (lane & 16) ? lo : hi;
            ACCF(i) = fadd2(mine, shflx64(give, 16));
        }
#pragma unroll
        for (int i = 0; i < 8; i++) {
            u64 lo = ACCF(i), hi = ACCF(i + 8);
            u64 mine = (lane & 8) ? hi : lo;
            u64 give = (lane & 8) ? lo : hi;
            ACCF(i) = fadd2(mine, shflx64(give, 8));
        }
#pragma unroll
        for (int i = 0; i < 4; i++) {
            u64 lo = ACCF(i), hi = ACCF(i + 4);
            u64 mine = (lane & 4) ? hi : lo;
            u64 give = (lane & 4) ? lo : hi;
            ACCF(i) = fadd2(mine, shflx64(give, 4));
        }
#pragma unroll
        for (int i = 0; i < 2; i++) {
            u64 lo = ACCF(i), hi = ACCF(i + 2);
            u64 mine = (lane & 2) ? hi : lo;
            u64 give = (lane & 2) ? lo : hi;
            ACCF(i) = fadd2(mine, shflx64(give, 2));
        }
        {
            u64 lo = ACCF(0), hi = ACCF(1);
            u64 mine = (lane & 1) ? hi : lo;
            u64 give = (lane & 1) ? lo : hi;
            ACCF(0) = fadd2(mine, shflx64(give, 1));
        }
        u64 fin = ACCF(0);

        // gather all 4 gates for batch (lane&7)
        u64 gv[4];
#pragma unroll
        for (int g = 0; g < 4; g++)
            gv[g] = fadd2(shfli64(fin, g * 8 + (lane & 7)), bias2[g]);

        float ig0 = sigf(f2lo(gv[0])), ig1 = sigf(f2hi(gv[0]));
        float fg0 = sigf(f2lo(gv[1])), fg1 = sigf(f2hi(gv[1]));
        float gg0 = tanhfast(f2lo(gv[2])), gg1 = tanhfast(f2hi(gv[2]));
        float og0 = sigf(f2lo(gv[3])), og1 = sigf(f2hi(gv[3]));
        c0r = fg0 * c0r + ig0 * gg0;
        c1r = fg1 * c1r + ig1 * gg1;
        float h0v = og0 * tanhfast(c0r);
        float h1v = og1 * tanhfast(c1r);

        if (lane < 8)
            *(float2*)&h_all[((size_t)t * BATCH + bbase + bb) * HID + hu0] =
                make_float2(h0v, h1v);

        // ---- grid barrier (epoch-relative, replay-safe) ----
        if (t + 1 < SEQ) {
            __threadfence();
            __syncthreads();
            if (tid == 0) {
                unsigned target = phase0 + (unsigned)(t + 1);
                unsigned old = atomicAdd(&g_arrive, 1u);
                if (old == (unsigned)(NCTA - 1)) {
                    g_arrive = 0u;
                    __threadfence();
                    atomicAdd(&g_phase, 1u);
                } else {
                    while ((int)(ld_acq(&g_phase) - target) < 0) __nanosleep(64);
                }
            }
            __syncthreads();
        }
    }
#undef ACCF
}

// ---------------- output head: sigmoid(h1 . w_out + b_out) ----------------
__global__ void __launch_bounds__(256)
head_kernel(const float* __restrict__ h_all, const float* __restrict__ w_out,
            const float* __restrict__ b_out, float* __restrict__ out)
{
    __shared__ float wsm[HID];
    int t = blockIdx.x;
    for (int i = threadIdx.x; i < HID; i += 256) wsm[i] = w_out[i];
    __syncthreads();
    int wrp = threadIdx.x >> 5, lane = threadIdx.x & 31;
    float bo = b_out[0];
#pragma unroll
    for (int rb = 0; rb < 8; ++rb) {
        int b = wrp * 8 + rb;
        const float* h = h_all + ((size_t)t * BATCH + b) * HID;
        float s = 0.f;
#pragma unroll
        for (int j = 0; j < 16; ++j) s += h[lane + 32 * j] * wsm[lane + 32 * j];
#pragma unroll
        for (int m = 16; m > 0; m >>= 1) s += __shfl_xor_sync(0xffffffffu, s, m);
        if (lane == 0) out[(size_t)t * BATCH + b] = 1.f / (1.f + expf(-(s + bo)));
    }
}

extern "C" void kernel_launch(void* const* d_in, const int* in_sizes, int n_in,
                              void* d_out, int out_size)
{
    (void)in_sizes; (void)n_in; (void)out_size;
    const float* input = (const float*)d_in[0];
    const float* h0    = (const float*)d_in[1];
    const float* c0    = (const float*)d_in[2];
    const float* w_ih0 = (const float*)d_in[3];
    const float* w_hh0 = (const float*)d_in[4];
    const float* b_ih0 = (const float*)d_in[5];
    const float* b_hh0 = (const float*)d_in[6];
    const float* w_ih1 = (const float*)d_in[7];
    const float* w_hh1 = (const float*)d_in[8];
    const float* b_ih1 = (const float*)d_in[9];
    const float* b_hh1 = (const float*)d_in[10];
    const float* w_out = (const float*)d_in[11];
    const float* b_out = (const float*)d_in[12];
    float* out = (float*)d_out;

    float* h0p = nullptr;
    float* h1p = nullptr;
    cudaGetSymbolAddress((void**)&h0p, g_h0_all);
    cudaGetSymbolAddress((void**)&h1p, g_h1_all);

    const int smem0 = (768 * 32 + 768 * 33 + 32) * (int)sizeof(float);   // 199,808
    const int smem1 = (1024 * 32 + 512 * 33 + 32) * (int)sizeof(float);  // 198,784
    cudaFuncSetAttribute(lstm_layer<256>, cudaFuncAttributeMaxDynamicSharedMemorySize, smem0);
    cudaFuncSetAttribute(lstm_layer<512>, cudaFuncAttributeMaxDynamicSharedMemorySize, smem1);

    lstm_layer<256><<<NCTA, NTHR, smem0>>>(input, h0, c0,
                                           w_ih0, w_hh0, b_ih0, b_hh0, h0p);
    lstm_layer<512><<<NCTA, NTHR, smem1>>>(h0p, h0 + BATCH * HID, c0 + BATCH * HID,
                                           w_ih1, w_hh1, b_ih1, b_hh1, h1p);
    head_kernel<<<SEQ, 256>>>(h1p, w_out, b_out, out);
}

// round 5
// speedup vs baseline: 2.3788x; 1.1765x over previous
#include <cuda_runtime.h>
#include <cstdint>
#include <cstddef>
#include <math.h>

#define SEQ    2048
#define BATCH  64
#define HID    512
#define NCTA   128
#define NTHR   512

typedef unsigned long long u64;

// ---------------- device globals (allocation-free scratch) ----------------
__device__ unsigned g_arrive = 0;
__device__ unsigned g_phase  = 0;
__device__ float g_h0_all[(size_t)SEQ * BATCH * HID];
__device__ float g_h1_all[(size_t)SEQ * BATCH * HID];

// ---------------- packed fp32x2 helpers ----------------
__device__ __forceinline__ u64 ffma2(u64 a, u64 b, u64 c) {
    u64 d;
    asm("fma.rn.f32x2 %0, %1, %2, %3;" : "=l"(d) : "l"(a), "l"(b), "l"(c));
    return d;
}
__device__ __forceinline__ u64 fadd2(u64 a, u64 b) {
    u64 d;
    asm("add.rn.f32x2 %0, %1, %2;" : "=l"(d) : "l"(a), "l"(b));
    return d;
}
__device__ __forceinline__ u64 splat2(float x) {
    u64 d;
    asm("mov.b64 %0, {%1, %1};" : "=l"(d) : "f"(x));
    return d;
}
__device__ __forceinline__ float f2lo(u64 v) { return __uint_as_float((unsigned)v); }
__device__ __forceinline__ float f2hi(u64 v) { return __uint_as_float((unsigned)(v >> 32)); }

__device__ __forceinline__ u64 shflx64(u64 v, int m) {
    unsigned lo = (unsigned)v, hi = (unsigned)(v >> 32);
    lo = __shfl_xor_sync(0xffffffffu, lo, m);
    hi = __shfl_xor_sync(0xffffffffu, hi, m);
    return ((u64)hi << 32) | (u64)lo;
}
__device__ __forceinline__ u64 shfli64(u64 v, int src) {
    unsigned lo = (unsigned)v, hi = (unsigned)(v >> 32);
    lo = __shfl_sync(0xffffffffu, lo, src);
    hi = __shfl_sync(0xffffffffu, hi, src);
    return ((u64)hi << 32) | (u64)lo;
}
__device__ __forceinline__ unsigned ld_acq(unsigned* p) {
    unsigned v;
    asm volatile("ld.acquire.gpu.u32 %0, [%1];" : "=r"(v) : "l"(p));
    return v;
}
__device__ __forceinline__ float sigf(float x) { return 1.0f / (1.0f + __expf(-x)); }
__device__ __forceinline__ float tanhfast(float x) {
    return 2.0f / (1.0f + __expf(-2.0f * x)) - 1.0f;
}

// =====================================================================
// Persistent fused LSTM layer, v3: cross-step software pipeline.
//  - 256-k chunks, two act buffers, stage(next) overlapped with compute.
//  - x-projection of step t+1 computed AFTER the barrier arrive of step t
//    and BEFORE the phase wait -> barrier latency hidden behind real work.
//  - 128 CTAs x 512 thr; CTA = 8 hu x 32 batches; k-split 32 per warp;
//    micro-tile 4 gate-pairs x 8 batches as f32x2 -> FFMA2.
// =====================================================================
template<int DIN>
__global__ void __launch_bounds__(NTHR, 1)
lstm_layer(const float* __restrict__ x,       // [SEQ][BATCH][DIN]
           const float* __restrict__ h0l,     // [BATCH][HID]
           const float* __restrict__ c0l,     // [BATCH][HID]
           const float* __restrict__ w_ih,    // [4H][DIN]
           const float* __restrict__ w_hh,    // [4H][HID]
           const float* __restrict__ b_ih,    // [4H]
           const float* __restrict__ b_hh,    // [4H]
           float* __restrict__ h_all)         // [SEQ][BATCH][HID]
{
    constexpr int K   = HID + DIN;              // 768 or 1024
    constexpr int NXC = DIN / 256;               // 1 or 2 x-chunks

    extern __shared__ float smem[];
    float* w_sm    = smem;                       // K*32
    float* buf0    = w_sm + K * 32;              // 256*33
    float* buf1    = buf0 + 256 * 33;            // 256*33
    float* bias_sm = buf1 + 256 * 33;            // 32 (pair-major)

    const int tid  = threadIdx.x;
    const int lane = tid & 31;
    const int wrp  = tid >> 5;                   // 0..15
    const int rg   = wrp & 3;
    const int bg   = wrp >> 2;
    const int hu_base = (blockIdx.x >> 1) * 8;
    const int bbase   = (blockIdx.x & 1) * 32;

    // ---- one-time: weights (swizzled) + bias into SMEM ----
    for (int r = 0; r < 32; r++) {
        int gate = r >> 3, hl = r & 7;
        int R = gate * HID + hu_base + hl;
        int pair = gate * 4 + (hl >> 1);
        const float* wr_h = w_hh + (size_t)R * HID;
        const float* wr_x = w_ih + (size_t)R * DIN;
        for (int k = tid; k < K; k += NTHR) {
            float v = (k < HID) ? wr_h[k] : wr_x[k - HID];
            int col = ((pair ^ (k & 15)) << 1) | (hl & 1);
            w_sm[k * 32 + col] = v;
        }
    }
    if (tid < 32) {
        int gate = tid >> 3, hl = tid & 7;
        int R = gate * HID + hu_base + hl;
        int pair = gate * 4 + (hl >> 1);
        bias_sm[pair * 2 + (hl & 1)] = b_ih[R] + b_hh[R];
    }

    __shared__ unsigned s_p0;
    if (tid == 0) s_p0 = ld_acq(&g_phase);
    __syncthreads();
    const unsigned phase0 = s_p0;

    u64 bias2[4];
#pragma unroll
    for (int g = 0; g < 4; g++) bias2[g] = ((const u64*)bias_sm)[g * 4 + rg];

    int colg[4];
#pragma unroll
    for (int g = 0; g < 4; g++) colg[g] = (((g * 4 + rg) ^ (lane & 15)) << 1);

    const int bb  = bg * 8 + (lane & 7);
    const int hu0 = hu_base + rg * 2;
    float c0r = c0l[(size_t)(bbase + bb) * HID + hu0];
    float c1r = c0l[(size_t)(bbase + bb) * HID + hu0 + 1];

    u64 acc[4][8];
#pragma unroll
    for (int g = 0; g < 4; g++)
#pragma unroll
        for (int b = 0; b < 8; b++) acc[g][b] = 0ull;

    // ---- helpers (inlined lambdas) ----
    auto stage = [&](float* buf, const float* src, int stride, int koff) {
#pragma unroll
        for (int p = 0; p < 2; p++) {
            const int b = wrp + p * 16;
            const float* r = src + (size_t)(bbase + b) * stride + koff + lane;
#pragma unroll
            for (int q = 0; q < 8; q++)
                buf[(q * 32 + lane) * 33 + b] = __ldg(r + q * 32);
        }
    };
    auto compute = [&](const float* buf, int kbase) {
        const float* wl = w_sm + (size_t)(kbase + lane) * 32;
        const float* ab = buf + lane * 33 + bg * 8;
#pragma unroll
        for (int j = 0; j < 8; j++) {
            u64 w2[4];
#pragma unroll
            for (int g = 0; g < 4; g++)
                w2[g] = *(const u64*)(wl + j * (32 * 32) + colg[g]);
            float a[8];
#pragma unroll
            for (int b = 0; b < 8; b++) a[b] = ab[j * (32 * 33) + b];
#pragma unroll
            for (int b = 0; b < 8; b++) {
                u64 a2 = splat2(a[b]);
#pragma unroll
                for (int g = 0; g < 4; g++)
                    acc[g][b] = ffma2(w2[g], a2, acc[g][b]);
            }
        }
    };

#define ACCF(i) acc[(i) >> 3][(i) & 7]

    // ---- prologue: x-projection of step 0 into acc ----
    {
        const float* xt = x;                    // t = 0
        stage(buf0, xt, DIN, 0);
        __syncthreads();
        if constexpr (NXC == 2) {
            stage(buf1, xt, DIN, 256);
            compute(buf0, HID);
            __syncthreads();
            compute(buf1, HID + 256);
        } else {
            compute(buf0, HID);
        }
    }

    for (int t = 0; t < SEQ; ++t) {
        const float* __restrict__ hprev =
            t ? (h_all + (size_t)(t - 1) * BATCH * HID) : h0l;

        // barrier wait for h(t-1) (arrive happened last step, before x work)
        if (t > 0 && tid == 0) {
            unsigned target = phase0 + (unsigned)t;
            if ((int)(ld_acq(&g_phase) - target) < 0) {
                while ((int)(ld_acq(&g_phase) - target) < 0) __nanosleep(32);
            }
        }
        __syncthreads();   // also separates prior compute from Hc0 staging

        // ---- h-part: 2 chunks, pipelined ----
        stage(buf0, hprev, HID, 0);
        __syncthreads();
        stage(buf1, hprev, HID, 256);
        compute(buf0, 0);
        __syncthreads();
        if (t + 1 < SEQ) {
            // pre-stage x chunk 0 of step t+1 (no barrier dependency)
            const float* xn = x + (size_t)(t + 1) * BATCH * DIN;
            stage(buf0, xn, DIN, 0);
        }
        compute(buf1, 256);

        // ---- intra-warp reduction over 32 k-lanes ----
#pragma unroll
        for (int i = 0; i < 16; i++) {
            u64 lo = ACCF(i), hi = ACCF(i + 16);
            u64 mine = (lane & 16) ? hi : lo;
            u64 give = (lane & 16) ? lo : hi;
            ACCF(i) = fadd2(mine, shflx64(give, 16));
        }
#pragma unroll
        for (int i = 0; i < 8; i++) {
            u64 lo = ACCF(i), hi = ACCF(i + 8);
            u64 mine = (lane & 8) ? hi : lo;
            u64 give = (lane & 8) ? lo : hi;
            ACCF(i) = fadd2(mine, shflx64(give, 8));
        }
#pragma unroll
        for (int i = 0; i < 4; i++) {
            u64 lo = ACCF(i), hi = ACCF(i + 4);
            u64 mine = (lane & 4) ? hi : lo;
            u64 give = (lane & 4) ? lo : hi;
            ACCF(i) = fadd2(mine, shflx64(give, 4));
        }
#pragma unroll
        for (int i = 0; i < 2; i++) {
            u64 lo = ACCF(i), hi = ACCF(i + 2);
            u64 mine = (lane & 2) ? hi : lo;
            u64 give = (lane & 2) ? lo : hi;
            ACCF(i) = fadd2(mine, shflx64(give, 2));
        }
        {
            u64 lo = ACCF(0), hi = ACCF(1);
            u64 mine = (lane & 1) ? hi : lo;
            u64 give = (lane & 1) ? lo : hi;
            ACCF(0) = fadd2(mine, shflx64(give, 1));
        }
        u64 fin = ACCF(0);

        u64 gv[4];
#pragma unroll
        for (int g = 0; g < 4; g++)
            gv[g] = fadd2(shfli64(fin, g * 8 + (lane & 7)), bias2[g]);

        float ig0 = sigf(f2lo(gv[0])), ig1 = sigf(f2hi(gv[0]));
        float fg0 = sigf(f2lo(gv[1])), fg1 = sigf(f2hi(gv[1]));
        float gg0 = tanhfast(f2lo(gv[2])), gg1 = tanhfast(f2hi(gv[2]));
        float og0 = sigf(f2lo(gv[3])), og1 = sigf(f2hi(gv[3]));
        c0r = fg0 * c0r + ig0 * gg0;
        c1r = fg1 * c1r + ig1 * gg1;
        float h0v = og0 * tanhfast(c0r);
        float h1v = og1 * tanhfast(c1r);

        if (lane < 8)
            *(float2*)&h_all[((size_t)t * BATCH + bbase + bb) * HID + hu0] =
                make_float2(h0v, h1v);

        // zero acc for next step's x accumulation
#pragma unroll
        for (int g = 0; g < 4; g++)
#pragma unroll
            for (int b = 0; b < 8; b++) acc[g][b] = 0ull;

        if (t + 1 < SEQ) {
            __threadfence();
            __syncthreads();          // all h stores fenced; Xc0 STS complete
            if (tid == 0) {
                unsigned old = atomicAdd(&g_arrive, 1u);
                if (old == (unsigned)(NCTA - 1)) {
                    g_arrive = 0u;
                    __threadfence();
                    atomicAdd(&g_phase, 1u);
                }
            }
            // x-projection of step t+1 (overlaps other CTAs' progress)
            const float* xn = x + (size_t)(t + 1) * BATCH * DIN;
            if constexpr (NXC == 2) {
                stage(buf1, xn, DIN, 256);
                compute(buf0, HID);
                __syncthreads();
                compute(buf1, HID + 256);
            } else {
                compute(buf0, HID);
            }
        }
    }
#undef ACCF
}

// ---------------- output head ----------------
__global__ void __launch_bounds__(256)
head_kernel(const float* __restrict__ h_all, const float* __restrict__ w_out,
            const float* __restrict__ b_out, float* __restrict__ out)
{
    __shared__ float wsm[HID];
    int t = blockIdx.x;
    for (int i = threadIdx.x; i < HID; i += 256) wsm[i] = w_out[i];
    __syncthreads();
    int wrp = threadIdx.x >> 5, lane = threadIdx.x & 31;
    float bo = b_out[0];
#pragma unroll
    for (int rb = 0; rb < 8; ++rb) {
        int b = wrp * 8 + rb;
        const float* h = h_all + ((size_t)t * BATCH + b) * HID;
        float s = 0.f;
#pragma unroll
        for (int j = 0; j < 16; ++j) s += h[lane + 32 * j] * wsm[lane + 32 * j];
#pragma unroll
        for (int m = 16; m > 0; m >>= 1) s += __shfl_xor_sync(0xffffffffu, s, m);
        if (lane == 0) out[(size_t)t * BATCH + b] = 1.f / (1.f + expf(-(s + bo)));
    }
}

extern "C" void kernel_launch(void* const* d_in, const int* in_sizes, int n_in,
                              void* d_out, int out_size)
{
    (void)in_sizes; (void)n_in; (void)out_size;
    const float* input = (const float*)d_in[0];
    const float* h0    = (const float*)d_in[1];
    const float* c0    = (const float*)d_in[2];
    const float* w_ih0 = (const float*)d_in[3];
    const float* w_hh0 = (const float*)d_in[4];
    const float* b_ih0 = (const float*)d_in[5];
    const float* b_hh0 = (const float*)d_in[6];
    const float* w_ih1 = (const float*)d_in[7];
    const float* w_hh1 = (const float*)d_in[8];
    const float* b_ih1 = (const float*)d_in[9];
    const float* b_hh1 = (const float*)d_in[10];
    const float* w_out = (const float*)d_in[11];
    const float* b_out = (const float*)d_in[12];
    float* out = (float*)d_out;

    float* h0p = nullptr;
    float* h1p = nullptr;
    cudaGetSymbolAddress((void**)&h0p, g_h0_all);
    cudaGetSymbolAddress((void**)&h1p, g_h1_all);

    const int smem0 = (768  * 32 + 2 * 256 * 33 + 32) * (int)sizeof(float); // 165,888+
    const int smem1 = (1024 * 32 + 2 * 256 * 33 + 32) * (int)sizeof(float); // 198,656+
    cudaFuncSetAttribute(lstm_layer<256>, cudaFuncAttributeMaxDynamicSharedMemorySize, smem0);
    cudaFuncSetAttribute(lstm_layer<512>, cudaFuncAttributeMaxDynamicSharedMemorySize, smem1);

    lstm_layer<256><<<NCTA, NTHR, smem0>>>(input, h0, c0,
                                           w_ih0, w_hh0, b_ih0, b_hh0, h0p);
    lstm_layer<512><<<NCTA, NTHR, smem1>>>(h0p, h0 + BATCH * HID, c0 + BATCH * HID,
                                           w_ih1, w_hh1, b_ih1, b_hh1, h1p);
    head_kernel<<<SEQ, 256>>>(h1p, w_out, b_out, out);
}